// round 7
// baseline (speedup 1.0000x reference)
#include <cuda_runtime.h>
#include <cstddef>

// Problem constants
constexpr int NB  = 4;
constexpr int NS  = 2048;
constexpr int ND  = 1024;
constexpr int NH  = 16;
constexpr int NDK = 64;
constexpr int NBS = NB * NS;          // 8192

// Scratch (static device globals — no allocation)
__device__ float g_q[(size_t)NB * NH * NS * NDK];   // [B,H,S,DK]
__device__ float g_k[(size_t)NB * NH * NS * NDK];
__device__ float g_v[(size_t)NB * NH * NS * NDK];
__device__ float g_cat[(size_t)NBS * NH * NDK];     // [B*S, H*DK]

// ---------------------------------------------------------------------------
// tf32 helpers
// ---------------------------------------------------------------------------
__device__ __forceinline__ float f2tff(float f) {
    unsigned u;
    asm("cvt.rna.tf32.f32 %0, %1;" : "=r"(u) : "f"(f));
    return __uint_as_float(u);
}

// D += A(16x8,row) * B(8x8,col), tf32 inputs, fp32 accum
__device__ __forceinline__ void mma8(float* c, const unsigned* a, const unsigned* b) {
    asm volatile(
        "mma.sync.aligned.m16n8k8.row.col.f32.tf32.tf32.f32 "
        "{%0,%1,%2,%3}, {%4,%5,%6,%7}, {%8,%9}, {%0,%1,%2,%3};"
        : "+f"(c[0]), "+f"(c[1]), "+f"(c[2]), "+f"(c[3])
        : "r"(a[0]), "r"(a[1]), "r"(a[2]), "r"(a[3]), "r"(b[0]), "r"(b[1]));
}

// k-permutation within a BK=32 slice: pos = (k&3)*8 + (k>>2)
__device__ __forceinline__ int perm32(int k) { return (k & 3) * 8 + (k >> 2); }
// k-permutation for 64-wide k with per-tg float4-group rotation (bank-safe @pitch 80)
__device__ __forceinline__ int perm64(int k) {
    int t = k & 3, c = k >> 2;
    return t * 16 + ((((c >> 2) + t) & 3) << 2) + (c & 3);
}

// ---------------------------------------------------------------------------
// Kernel 1: QKV projections via tf32 MMA, permuted smem + LDS.128 fragments.
// Block tile 256(M) x 64(N=DK) per (head, mat). 8 warps 4x2 -> warp 64x32.
// ---------------------------------------------------------------------------
__global__ __launch_bounds__(256) void qkv_kernel(
    const float* __restrict__ x,
    const float* __restrict__ Wq, const float* __restrict__ bq,
    const float* __restrict__ Wk, const float* __restrict__ bk,
    const float* __restrict__ Wv, const float* __restrict__ bv)
{
    __shared__ __align__(16) float As[256 * 36];   // [row][k-perm], pitch 36
    __shared__ __align__(16) float Bsf[64 * 36];   // [n][k-perm],   pitch 36

    const int h   = blockIdx.y;
    const int mat = blockIdx.z;
    const float* W    = (mat == 0) ? Wq : (mat == 1) ? Wk : Wv;
    const float* bias = (mat == 0) ? bq : (mat == 1) ? bk : bv;
    float* dst        = (mat == 0) ? g_q : (mat == 1) ? g_k : g_v;

    const int m0   = blockIdx.x * 256;
    const int tid  = threadIdx.x;
    const int warp = tid >> 5, lane = tid & 31;
    const int g = lane >> 2, tg = lane & 3;
    const int wm = warp >> 1, wn = warp & 1;

    float acc[4][4][4] = {};
    const float* Wh = W + (size_t)h * ND * NDK;

    for (int kk = 0; kk < ND; kk += 32) {
        // Stage A 256x32 (k-permuted): 8 float4 per thread
        #pragma unroll
        for (int t = 0; t < 8; t++) {
            int f = tid + t * 256;
            int r = f >> 3, c4 = (f & 7) * 4;
            float4 v = *(const float4*)(x + (size_t)(m0 + r) * ND + kk + c4);
            int base = r * 36 + (c4 >> 2);
            As[base +  0] = f2tff(v.x);
            As[base +  8] = f2tff(v.y);
            As[base + 16] = f2tff(v.z);
            As[base + 24] = f2tff(v.w);
        }
        // Stage B 32x64 transposed to [n][k-perm]: 2 float4 per thread
        #pragma unroll
        for (int t = 0; t < 2; t++) {
            int f = tid + t * 256;
            int r = f >> 4, c4 = (f & 15) * 4;
            float4 v = *(const float4*)(Wh + (size_t)(kk + r) * NDK + c4);
            int pk = perm32(r);
            Bsf[(c4 + 0) * 36 + pk] = f2tff(v.x);
            Bsf[(c4 + 1) * 36 + pk] = f2tff(v.y);
            Bsf[(c4 + 2) * 36 + pk] = f2tff(v.z);
            Bsf[(c4 + 3) * 36 + pk] = f2tff(v.w);
        }
        __syncthreads();

        #pragma unroll
        for (int j = 0; j < 2; j++) {
            uint4 af0[4], af1[4];
            #pragma unroll
            for (int mt = 0; mt < 4; mt++) {
                int rA = wm * 64 + mt * 16 + g;
                af0[mt] = *(const uint4*)&As[rA * 36 + tg * 8 + 4 * j];
                af1[mt] = *(const uint4*)&As[(rA + 8) * 36 + tg * 8 + 4 * j];
            }
            #pragma unroll
            for (int nt = 0; nt < 4; nt++) {
                uint4 bf = *(const uint4*)&Bsf[(wn * 32 + nt * 8 + g) * 36 + tg * 8 + 4 * j];
                unsigned be[2] = {bf.x, bf.y};
                unsigned bo[2] = {bf.z, bf.w};
                #pragma unroll
                for (int mt = 0; mt < 4; mt++) {
                    unsigned ae[4] = {af0[mt].x, af1[mt].x, af0[mt].y, af1[mt].y};
                    unsigned ao[4] = {af0[mt].z, af1[mt].z, af0[mt].w, af1[mt].w};
                    mma8(acc[mt][nt], ae, be);
                    mma8(acc[mt][nt], ao, bo);
                }
            }
        }
        __syncthreads();
    }

    // Epilogue: + bias, write to [B,H,S,DK]
    #pragma unroll
    for (int nt = 0; nt < 4; nt++) {
        int cc = wn * 32 + nt * 8 + 2 * tg;
        float b0 = bias[h * NDK + cc], b1 = bias[h * NDK + cc + 1];
        #pragma unroll
        for (int mt = 0; mt < 4; mt++) {
            #pragma unroll
            for (int p = 0; p < 2; p++) {
                int rr = wm * 64 + mt * 16 + g + p * 8;
                int m  = m0 + rr;
                int b_ = m / NS, s = m % NS;
                float2 v;
                v.x = acc[mt][nt][2 * p + 0] + b0;
                v.y = acc[mt][nt][2 * p + 1] + b1;
                *(float2*)(dst + ((((size_t)b_ * NH + h) * NS + s) * NDK) + cc) = v;
            }
        }
    }
}

// ---------------------------------------------------------------------------
// Kernel 2: causal flash attention, tf32 MMA, permuted smem + LDS.128 frags.
// 128 threads (4 warps). Q tile 64 rows (16/warp, Q in registers), key tile 64.
// KP buffer holds Q, then K (S-phase), then P (PV-phase). Pitch 80, perm64.
// ---------------------------------------------------------------------------
__global__ __launch_bounds__(128) void attn_kernel()
{
    __shared__ __align__(16) float KP[64 * 80];
    __shared__ __align__(16) float Vs[64 * 80];

    const int qt = (int)(gridDim.x - 1) - (int)blockIdx.x;  // heavy first
    const int bh = blockIdx.y;
    const int q0 = qt * 64;
    const float* qb = g_q + (size_t)bh * NS * NDK;
    const float* kb = g_k + (size_t)bh * NS * NDK;
    const float* vb = g_v + (size_t)bh * NS * NDK;

    const int tid = threadIdx.x;
    const int w = tid >> 5, lane = tid & 31;
    const int g = lane >> 2, tg = lane & 3;

    // Stage Q tile (k=feature perm) into KP
    #pragma unroll
    for (int t = 0; t < 8; t++) {
        int f = tid + t * 128;
        int r = f >> 4, c4 = (f & 15) * 4;
        float4 v = *(const float4*)(qb + (size_t)(q0 + r) * NDK + c4);
        int cc = c4 >> 2, rb = r * 80;
        KP[rb + perm64(c4 + 0)] = f2tff(v.x);
        KP[rb + perm64(c4 + 1)] = f2tff(v.y);
        KP[rb + perm64(c4 + 2)] = f2tff(v.z);
        KP[rb + perm64(c4 + 3)] = f2tff(v.w);
        (void)cc;
    }
    __syncthreads();

    // Q fragments for all 8 k-steps, via 8 LDS.128
    unsigned qa[8][4];
    #pragma unroll
    for (int j = 0; j < 4; j++) {
        int off = tg * 16 + (((j + tg) & 3) << 2);
        uint4 q0f = *(const uint4*)&KP[(w * 16 + g) * 80 + off];
        uint4 q1f = *(const uint4*)&KP[(w * 16 + 8 + g) * 80 + off];
        qa[2 * j][0] = q0f.x; qa[2 * j][1] = q1f.x; qa[2 * j][2] = q0f.y; qa[2 * j][3] = q1f.y;
        qa[2 * j + 1][0] = q0f.z; qa[2 * j + 1][1] = q1f.z; qa[2 * j + 1][2] = q0f.w; qa[2 * j + 1][3] = q1f.w;
    }

    float oacc[8][4] = {};
    float m_i[2] = {-3.0e38f, -3.0e38f};
    float l_i[2] = {0.f, 0.f};

    for (int jt = 0; jt <= qt; jt++) {
        __syncthreads();   // prior-iter KP/Vs reads complete
        const int kc0 = jt * 64;
        #pragma unroll
        for (int t = 0; t < 8; t++) {
            int f = tid + t * 128;
            int r = f >> 4, c4 = (f & 15) * 4;
            float4 kv = *(const float4*)(kb + (size_t)(kc0 + r) * NDK + c4);
            int rb = r * 80;
            KP[rb + perm64(c4 + 0)] = f2tff(kv.x);
            KP[rb + perm64(c4 + 1)] = f2tff(kv.y);
            KP[rb + perm64(c4 + 2)] = f2tff(kv.z);
            KP[rb + perm64(c4 + 3)] = f2tff(kv.w);
            float4 vv = *(const float4*)(vb + (size_t)(kc0 + r) * NDK + c4);
            int pk = perm64(r);   // key-index permutation (V stored transposed)
            Vs[(c4 + 0) * 80 + pk] = f2tff(vv.x);
            Vs[(c4 + 1) * 80 + pk] = f2tff(vv.y);
            Vs[(c4 + 2) * 80 + pk] = f2tff(vv.z);
            Vs[(c4 + 3) * 80 + pk] = f2tff(vv.w);
        }
        __syncthreads();

        // S = Q K^T  (warp: 16 x 64)
        float sacc[8][4] = {};
        #pragma unroll
        for (int j = 0; j < 4; j++) {
            int off = tg * 16 + (((j + tg) & 3) << 2);
            #pragma unroll
            for (int nt = 0; nt < 8; nt++) {
                uint4 kf = *(const uint4*)&KP[(nt * 8 + g) * 80 + off];
                unsigned be[2] = {kf.x, kf.y};
                unsigned bo[2] = {kf.z, kf.w};
                mma8(sacc[nt], qa[2 * j], be);
                mma8(sacc[nt], qa[2 * j + 1], bo);
            }
        }
        __syncthreads();   // all S reads of KP done before P overwrite

        // scale + causal mask
        const int r0 = q0 + w * 16 + g;
        if (jt == qt) {
            #pragma unroll
            for (int nt = 0; nt < 8; nt++) {
                int col = kc0 + nt * 8 + 2 * tg;
                sacc[nt][0] = (col     <= r0    ) ? sacc[nt][0] * 0.125f : -3.0e38f;
                sacc[nt][1] = (col + 1 <= r0    ) ? sacc[nt][1] * 0.125f : -3.0e38f;
                sacc[nt][2] = (col     <= r0 + 8) ? sacc[nt][2] * 0.125f : -3.0e38f;
                sacc[nt][3] = (col + 1 <= r0 + 8) ? sacc[nt][3] * 0.125f : -3.0e38f;
            }
        } else {
            #pragma unroll
            for (int nt = 0; nt < 8; nt++) {
                sacc[nt][0] *= 0.125f; sacc[nt][1] *= 0.125f;
                sacc[nt][2] *= 0.125f; sacc[nt][3] *= 0.125f;
            }
        }

        // row max
        float mt0 = -3.0e38f, mt1 = -3.0e38f;
        #pragma unroll
        for (int nt = 0; nt < 8; nt++) {
            mt0 = fmaxf(mt0, fmaxf(sacc[nt][0], sacc[nt][1]));
            mt1 = fmaxf(mt1, fmaxf(sacc[nt][2], sacc[nt][3]));
        }
        mt0 = fmaxf(mt0, __shfl_xor_sync(0xffffffffu, mt0, 1));
        mt0 = fmaxf(mt0, __shfl_xor_sync(0xffffffffu, mt0, 2));
        mt1 = fmaxf(mt1, __shfl_xor_sync(0xffffffffu, mt1, 1));
        mt1 = fmaxf(mt1, __shfl_xor_sync(0xffffffffu, mt1, 2));

        float mn0 = fmaxf(m_i[0], mt0), mn1 = fmaxf(m_i[1], mt1);
        float al0 = __expf(m_i[0] - mn0), al1 = __expf(m_i[1] - mn1);
        m_i[0] = mn0; m_i[1] = mn1;

        const int rb0 = (w * 16 + g) * 80;
        const int rb1 = rb0 + 8 * 80;
        float ls0 = 0.f, ls1 = 0.f;
        #pragma unroll
        for (int nt = 0; nt < 8; nt++) {
            float p0 = __expf(sacc[nt][0] - mn0);
            float p1 = __expf(sacc[nt][1] - mn0);
            float p2 = __expf(sacc[nt][2] - mn1);
            float p3 = __expf(sacc[nt][3] - mn1);
            ls0 += p0 + p1; ls1 += p2 + p3;
            int k0c = nt * 8 + 2 * tg;
            int pA = perm64(k0c), pB = perm64(k0c + 1);
            KP[rb0 + pA] = f2tff(p0); KP[rb0 + pB] = f2tff(p1);
            KP[rb1 + pA] = f2tff(p2); KP[rb1 + pB] = f2tff(p3);
            oacc[nt][0] *= al0; oacc[nt][1] *= al0;
            oacc[nt][2] *= al1; oacc[nt][3] *= al1;
        }
        ls0 += __shfl_xor_sync(0xffffffffu, ls0, 1);
        ls0 += __shfl_xor_sync(0xffffffffu, ls0, 2);
        ls1 += __shfl_xor_sync(0xffffffffu, ls1, 1);
        ls1 += __shfl_xor_sync(0xffffffffu, ls1, 2);
        l_i[0] = l_i[0] * al0 + ls0;
        l_i[1] = l_i[1] * al1 + ls1;

        __syncwarp();      // this warp's P rows written only by itself

        // O += P @ V  (warp: 16 x 64)
        #pragma unroll
        for (int j = 0; j < 4; j++) {
            int off = tg * 16 + (((j + tg) & 3) << 2);
            uint4 p0f = *(const uint4*)&KP[rb0 + off];
            uint4 p1f = *(const uint4*)&KP[rb1 + off];
            unsigned pe[4] = {p0f.x, p1f.x, p0f.y, p1f.y};
            unsigned po[4] = {p0f.z, p1f.z, p0f.w, p1f.w};
            #pragma unroll
            for (int nt = 0; nt < 8; nt++) {
                uint4 vf = *(const uint4*)&Vs[(nt * 8 + g) * 80 + off];
                unsigned be[2] = {vf.x, vf.y};
                unsigned bo[2] = {vf.z, vf.w};
                mma8(oacc[nt], pe, be);
                mma8(oacc[nt], po, bo);
            }
        }
    }

    // normalize + write to concat layout [B*S, H*DK]
    const float inv0 = 1.f / l_i[0], inv1 = 1.f / l_i[1];
    const int b_ = bh / NH, h_ = bh % NH;
    const size_t mrow = (size_t)b_ * NS + q0 + w * 16 + g;
    #pragma unroll
    for (int nt = 0; nt < 8; nt++) {
        int cc = h_ * NDK + nt * 8 + 2 * tg;
        *(float2*)&g_cat[ mrow      * (NH * NDK) + cc] =
            make_float2(oacc[nt][0] * inv0, oacc[nt][1] * inv0);
        *(float2*)&g_cat[(mrow + 8) * (NH * NDK) + cc] =
            make_float2(oacc[nt][2] * inv1, oacc[nt][3] * inv1);
    }
}

// ---------------------------------------------------------------------------
// Kernel 3: output projection, permuted smem + LDS.128 fragments.
// C[8192,1024] = g_cat @ Wo + bo. Block 128x128, 8 warps 4x2 -> warp 32x64.
// ---------------------------------------------------------------------------
__global__ __launch_bounds__(256) void proj_kernel(
    const float* __restrict__ Wo, const float* __restrict__ bo,
    float* __restrict__ out)
{
    __shared__ __align__(16) float As[128 * 36];
    __shared__ __align__(16) float Bsf[128 * 36];

    const int m0 = blockIdx.y * 128;
    const int n0 = blockIdx.x * 128;
    const int tid  = threadIdx.x;
    const int warp = tid >> 5, lane = tid & 31;
    const int g = lane >> 2, tg = lane & 3;
    const int wm = warp >> 1, wn = warp & 1;

    float acc[2][8][4] = {};

    for (int kk = 0; kk < ND; kk += 32) {
        // Stage A 128x32: 4 float4 per thread
        #pragma unroll
        for (int t = 0; t < 4; t++) {
            int f = tid + t * 256;
            int r = f >> 3, c4 = (f & 7) * 4;
            float4 v = *(const float4*)(g_cat + (size_t)(m0 + r) * ND + kk + c4);
            int base = r * 36 + (c4 >> 2);
            As[base +  0] = f2tff(v.x);
            As[base +  8] = f2tff(v.y);
            As[base + 16] = f2tff(v.z);
            As[base + 24] = f2tff(v.w);
        }
        // Stage B 32x128 transposed to [n][k-perm]: 4 float4 per thread
        #pragma unroll
        for (int t = 0; t < 4; t++) {
            int f = tid + t * 256;
            int r = f >> 5, c4 = (f & 31) * 4;
            float4 v = *(const float4*)(Wo + (size_t)(kk + r) * ND + n0 + c4);
            int pk = perm32(r);
            Bsf[(c4 + 0) * 36 + pk] = f2tff(v.x);
            Bsf[(c4 + 1) * 36 + pk] = f2tff(v.y);
            Bsf[(c4 + 2) * 36 + pk] = f2tff(v.z);
            Bsf[(c4 + 3) * 36 + pk] = f2tff(v.w);
        }
        __syncthreads();

        #pragma unroll
        for (int j = 0; j < 2; j++) {
            uint4 af0[2], af1[2];
            #pragma unroll
            for (int mt = 0; mt < 2; mt++) {
                int rA = wm * 32 + mt * 16 + g;
                af0[mt] = *(const uint4*)&As[rA * 36 + tg * 8 + 4 * j];
                af1[mt] = *(const uint4*)&As[(rA + 8) * 36 + tg * 8 + 4 * j];
            }
            #pragma unroll
            for (int nt = 0; nt < 8; nt++) {
                uint4 bf = *(const uint4*)&Bsf[(wn * 64 + nt * 8 + g) * 36 + tg * 8 + 4 * j];
                unsigned be[2] = {bf.x, bf.y};
                unsigned bo_[2] = {bf.z, bf.w};
                #pragma unroll
                for (int mt = 0; mt < 2; mt++) {
                    unsigned ae[4] = {af0[mt].x, af1[mt].x, af0[mt].y, af1[mt].y};
                    unsigned ao[4] = {af0[mt].z, af1[mt].z, af0[mt].w, af1[mt].w};
                    mma8(acc[mt][nt], ae, be);
                    mma8(acc[mt][nt], ao, bo_);
                }
            }
        }
        __syncthreads();
    }

    // Epilogue
    #pragma unroll
    for (int nt = 0; nt < 8; nt++) {
        int cc = wn * 64 + nt * 8 + 2 * tg;
        float b0 = bo[n0 + cc], b1 = bo[n0 + cc + 1];
        #pragma unroll
        for (int mt = 0; mt < 2; mt++) {
            #pragma unroll
            for (int p = 0; p < 2; p++) {
                int rr = wm * 32 + mt * 16 + g + p * 8;
                float2 v;
                v.x = acc[mt][nt][2 * p + 0] + b0;
                v.y = acc[mt][nt][2 * p + 1] + b1;
                *(float2*)(out + (size_t)(m0 + rr) * ND + n0 + cc) = v;
            }
        }
    }
}

// ---------------------------------------------------------------------------
extern "C" void kernel_launch(void* const* d_in, const int* in_sizes, int n_in,
                              void* d_out, int out_size)
{
    (void)in_sizes; (void)n_in; (void)out_size;
    const float* x  = (const float*)d_in[0];
    // d_in[1] = encoder_output (unused in the self-attention path)
    const float* Wq = (const float*)d_in[2];
    const float* bq = (const float*)d_in[3];
    const float* Wk = (const float*)d_in[4];
    const float* bk = (const float*)d_in[5];
    const float* Wv = (const float*)d_in[6];
    const float* bv = (const float*)d_in[7];
    const float* Wo = (const float*)d_in[8];
    const float* bo = (const float*)d_in[9];
    float* out = (float*)d_out;

    qkv_kernel<<<dim3(NBS / 256, NH, 3), 256>>>(x, Wq, bq, Wk, bk, Wv, bv);
    attn_kernel<<<dim3(NS / 64, NB * NH), 128>>>();
    proj_kernel<<<dim3(ND / 128, NBS / 128), 256>>>(Wo, bo, out);
}

// round 8
// speedup vs baseline: 1.8372x; 1.8372x over previous
#include <cuda_runtime.h>
#include <cstddef>

// Problem constants
constexpr int NB  = 4;
constexpr int NS  = 2048;
constexpr int ND  = 1024;
constexpr int NH  = 16;
constexpr int NDK = 64;
constexpr int NBS = NB * NS;          // 8192

// Scratch (static device globals — no allocation)
__device__ float g_q[(size_t)NB * NH * NS * NDK];   // [B,H,S,DK]
__device__ float g_k[(size_t)NB * NH * NS * NDK];
__device__ float g_v[(size_t)NB * NH * NS * NDK];
__device__ float g_cat[(size_t)NBS * NH * NDK];     // [B*S, H*DK]

// ---------------------------------------------------------------------------
// helpers
// ---------------------------------------------------------------------------
__device__ __forceinline__ float f2tff(float f) {
    unsigned u;
    asm("cvt.rna.tf32.f32 %0, %1;" : "=r"(u) : "f"(f));
    return __uint_as_float(u);
}

// D += A(16x8,row) * B(8x8,col), tf32 inputs, fp32 accum
__device__ __forceinline__ void mma8(float* c, const unsigned* a, const unsigned* b) {
    asm volatile(
        "mma.sync.aligned.m16n8k8.row.col.f32.tf32.tf32.f32 "
        "{%0,%1,%2,%3}, {%4,%5,%6,%7}, {%8,%9}, {%0,%1,%2,%3};"
        : "+f"(c[0]), "+f"(c[1]), "+f"(c[2]), "+f"(c[3])
        : "r"(a[0]), "r"(a[1]), "r"(a[2]), "r"(a[3]), "r"(b[0]), "r"(b[1]));
}

// ldmatrix x4: four 8x8 b16 tiles == four 8x4 fp32 tiles, one per dest reg
__device__ __forceinline__ void ldsm4(unsigned* r, const float* p) {
    unsigned a = (unsigned)__cvta_generic_to_shared(p);
    asm volatile("ldmatrix.sync.aligned.m8n8.x4.shared.b16 {%0,%1,%2,%3}, [%4];"
        : "=r"(r[0]), "=r"(r[1]), "=r"(r[2]), "=r"(r[3]) : "r"(a));
}

// lane-staggered rotation for transposed scalar staging stores
__device__ __forceinline__ int stag(int i, int tid) {
    return (i + (tid & 3) + ((tid >> 2) & 3) + ((tid >> 4) & 3)) & 3;
}

// ---------------------------------------------------------------------------
// Kernel 1: QKV projections via tf32 MMA + ldmatrix.
// Block tile 256(M) x 64(N=DK) per (head, mat). 8 warps 4x2 -> warp 64x32.
// As [m][k] pitch 36 (row-major), Bs [n][k] pitch 36 (transposed at store).
// ---------------------------------------------------------------------------
__global__ __launch_bounds__(256, 2) void qkv_kernel(
    const float* __restrict__ x,
    const float* __restrict__ Wq, const float* __restrict__ bq,
    const float* __restrict__ Wk, const float* __restrict__ bk,
    const float* __restrict__ Wv, const float* __restrict__ bv)
{
    __shared__ __align__(16) float As[256 * 36];
    __shared__ __align__(16) float Bs[64 * 36];

    const int h   = blockIdx.y;
    const int mat = blockIdx.z;
    const float* W    = (mat == 0) ? Wq : (mat == 1) ? Wk : Wv;
    const float* bias = (mat == 0) ? bq : (mat == 1) ? bk : bv;
    float* dst        = (mat == 0) ? g_q : (mat == 1) ? g_k : g_v;

    const int m0   = blockIdx.x * 256;
    const int tid  = threadIdx.x;
    const int warp = tid >> 5, lane = tid & 31;
    const int g = lane >> 2, tg = lane & 3;
    const int wm = warp >> 1, wn = warp & 1;

    // ldmatrix per-lane offsets
    const int aoff = (lane & 15) * 36 + (lane >> 4) * 4;                    // A frag
    const int boff = ((lane >> 4) * 8 + (lane & 7)) * 36 + ((lane >> 3) & 1) * 4; // B frag pair

    float acc[4][4][4] = {};
    const float* Wh = W + (size_t)h * ND * NDK;
    const float* AsW = As + (wm * 64) * 36;
    const float* BsW = Bs + (wn * 32) * 36;

    for (int kk = 0; kk < ND; kk += 32) {
        // Stage A 256x32 row-major: 8 float4 per thread
        #pragma unroll
        for (int t = 0; t < 8; t++) {
            int f = tid + t * 256;
            int r = f >> 3, c4 = (f & 7) * 4;
            float4 v = *(const float4*)(x + (size_t)(m0 + r) * ND + kk + c4);
            float4 w = make_float4(f2tff(v.x), f2tff(v.y), f2tff(v.z), f2tff(v.w));
            *(float4*)&As[r * 36 + c4] = w;
        }
        // Stage B 32x64 -> Bs[n][k]: 2 float4 per thread, staggered scatter
        #pragma unroll
        for (int t = 0; t < 2; t++) {
            int f = tid + t * 256;
            int r = f >> 4, c4 = (f & 15) * 4;
            float4 v = *(const float4*)(Wh + (size_t)(kk + r) * NDK + c4);
            float vs[4] = {f2tff(v.x), f2tff(v.y), f2tff(v.z), f2tff(v.w)};
            #pragma unroll
            for (int i = 0; i < 4; i++) {
                int p = stag(i, tid);
                Bs[(c4 + p) * 36 + r] = vs[p];
            }
        }
        __syncthreads();

        #pragma unroll
        for (int ks = 0; ks < 4; ks++) {
            const int k0 = ks * 8;
            unsigned a[4][4];
            #pragma unroll
            for (int mt = 0; mt < 4; mt++)
                ldsm4(a[mt], AsW + mt * 16 * 36 + aoff + k0);
            #pragma unroll
            for (int np = 0; np < 2; np++) {
                unsigned b4[4];
                ldsm4(b4, BsW + np * 16 * 36 + boff + k0);
                #pragma unroll
                for (int mt = 0; mt < 4; mt++) {
                    mma8(acc[mt][2 * np],     a[mt], &b4[0]);
                    mma8(acc[mt][2 * np + 1], a[mt], &b4[2]);
                }
            }
        }
        __syncthreads();
    }

    // Epilogue: + bias, write to [B,H,S,DK]
    #pragma unroll
    for (int nt = 0; nt < 4; nt++) {
        int cc = wn * 32 + nt * 8 + 2 * tg;
        float b0 = bias[h * NDK + cc], b1 = bias[h * NDK + cc + 1];
        #pragma unroll
        for (int mt = 0; mt < 4; mt++) {
            #pragma unroll
            for (int p = 0; p < 2; p++) {
                int rr = wm * 64 + mt * 16 + g + p * 8;
                int m  = m0 + rr;
                int b_ = m / NS, s = m % NS;
                float2 v;
                v.x = acc[mt][nt][2 * p + 0] + b0;
                v.y = acc[mt][nt][2 * p + 1] + b1;
                *(float2*)(dst + ((((size_t)b_ * NH + h) * NS + s) * NDK) + cc) = v;
            }
        }
    }
}

// ---------------------------------------------------------------------------
// Kernel 2: causal flash attention, tf32 MMA + ldmatrix.
// 128 threads (4 warps). Q tile 64 rows (16/warp, Q frags in regs), key tile 64.
// KP [row][feat] pitch 68 holds Q, then K, then P. Vs [feat][key] pitch 68.
// ---------------------------------------------------------------------------
__global__ __launch_bounds__(128) void attn_kernel()
{
    __shared__ __align__(16) float KP[64 * 68];
    __shared__ __align__(16) float Vs[64 * 68];

    const int qt = (int)(gridDim.x - 1) - (int)blockIdx.x;  // heavy first
    const int bh = blockIdx.y;
    const int q0 = qt * 64;
    const float* qb = g_q + (size_t)bh * NS * NDK;
    const float* kb = g_k + (size_t)bh * NS * NDK;
    const float* vb = g_v + (size_t)bh * NS * NDK;

    const int tid = threadIdx.x;
    const int w = tid >> 5, lane = tid & 31;
    const int g = lane >> 2, tg = lane & 3;

    const int aoff = (lane & 15) * 68 + (lane >> 4) * 4;
    const int boff = ((lane >> 4) * 8 + (lane & 7)) * 68 + ((lane >> 3) & 1) * 4;

    // Stage Q tile row-major
    #pragma unroll
    for (int t = 0; t < 8; t++) {
        int f = tid + t * 128;
        int r = f >> 4, c4 = (f & 15) * 4;
        float4 v = *(const float4*)(qb + (size_t)(q0 + r) * NDK + c4);
        float4 wv = make_float4(f2tff(v.x), f2tff(v.y), f2tff(v.z), f2tff(v.w));
        *(float4*)&KP[r * 68 + c4] = wv;
    }
    __syncthreads();

    // Q fragments for all 8 k-steps, 8 ldmatrix.x4
    unsigned qa[8][4];
    #pragma unroll
    for (int ks = 0; ks < 8; ks++)
        ldsm4(qa[ks], KP + (w * 16) * 68 + aoff + ks * 8);

    float oacc[8][4] = {};
    float m_i[2] = {-3.0e38f, -3.0e38f};
    float l_i[2] = {0.f, 0.f};

    for (int jt = 0; jt <= qt; jt++) {
        __syncthreads();   // prior-iter KP/Vs reads (and qa loads) complete
        const int kc0 = jt * 64;
        #pragma unroll
        for (int t = 0; t < 8; t++) {
            int f = tid + t * 128;
            int r = f >> 4, c4 = (f & 15) * 4;
            float4 kv = *(const float4*)(kb + (size_t)(kc0 + r) * NDK + c4);
            float4 kw = make_float4(f2tff(kv.x), f2tff(kv.y), f2tff(kv.z), f2tff(kv.w));
            *(float4*)&KP[r * 68 + c4] = kw;
            float4 vv = *(const float4*)(vb + (size_t)(kc0 + r) * NDK + c4);
            float vs[4] = {f2tff(vv.x), f2tff(vv.y), f2tff(vv.z), f2tff(vv.w)};
            #pragma unroll
            for (int i = 0; i < 4; i++) {
                int p = stag(i, tid);
                Vs[(c4 + p) * 68 + r] = vs[p];   // transposed [feat][key]
            }
        }
        __syncthreads();

        // S = Q K^T  (warp: 16 x 64)
        float sacc[8][4] = {};
        #pragma unroll
        for (int ks = 0; ks < 8; ks++) {
            #pragma unroll
            for (int np = 0; np < 4; np++) {
                unsigned kb4[4];
                ldsm4(kb4, KP + np * 16 * 68 + boff + ks * 8);
                mma8(sacc[2 * np],     qa[ks], &kb4[0]);
                mma8(sacc[2 * np + 1], qa[ks], &kb4[2]);
            }
        }
        __syncthreads();   // all S reads of KP done before P overwrite

        // scale + causal mask
        const int r0 = q0 + w * 16 + g;
        if (jt == qt) {
            #pragma unroll
            for (int nt = 0; nt < 8; nt++) {
                int col = kc0 + nt * 8 + 2 * tg;
                sacc[nt][0] = (col     <= r0    ) ? sacc[nt][0] * 0.125f : -3.0e38f;
                sacc[nt][1] = (col + 1 <= r0    ) ? sacc[nt][1] * 0.125f : -3.0e38f;
                sacc[nt][2] = (col     <= r0 + 8) ? sacc[nt][2] * 0.125f : -3.0e38f;
                sacc[nt][3] = (col + 1 <= r0 + 8) ? sacc[nt][3] * 0.125f : -3.0e38f;
            }
        } else {
            #pragma unroll
            for (int nt = 0; nt < 8; nt++) {
                sacc[nt][0] *= 0.125f; sacc[nt][1] *= 0.125f;
                sacc[nt][2] *= 0.125f; sacc[nt][3] *= 0.125f;
            }
        }

        // row max
        float mt0 = -3.0e38f, mt1 = -3.0e38f;
        #pragma unroll
        for (int nt = 0; nt < 8; nt++) {
            mt0 = fmaxf(mt0, fmaxf(sacc[nt][0], sacc[nt][1]));
            mt1 = fmaxf(mt1, fmaxf(sacc[nt][2], sacc[nt][3]));
        }
        mt0 = fmaxf(mt0, __shfl_xor_sync(0xffffffffu, mt0, 1));
        mt0 = fmaxf(mt0, __shfl_xor_sync(0xffffffffu, mt0, 2));
        mt1 = fmaxf(mt1, __shfl_xor_sync(0xffffffffu, mt1, 1));
        mt1 = fmaxf(mt1, __shfl_xor_sync(0xffffffffu, mt1, 2));

        float mn0 = fmaxf(m_i[0], mt0), mn1 = fmaxf(m_i[1], mt1);
        float al0 = __expf(m_i[0] - mn0), al1 = __expf(m_i[1] - mn1);
        m_i[0] = mn0; m_i[1] = mn1;

        const int rb0 = (w * 16 + g) * 68;
        const int rb1 = rb0 + 8 * 68;
        float ls0 = 0.f, ls1 = 0.f;
        #pragma unroll
        for (int nt = 0; nt < 8; nt++) {
            float p0 = __expf(sacc[nt][0] - mn0);
            float p1 = __expf(sacc[nt][1] - mn0);
            float p2 = __expf(sacc[nt][2] - mn1);
            float p3 = __expf(sacc[nt][3] - mn1);
            ls0 += p0 + p1; ls1 += p2 + p3;
            int cl = nt * 8 + 2 * tg;
            *(float2*)&KP[rb0 + cl] = make_float2(f2tff(p0), f2tff(p1));
            *(float2*)&KP[rb1 + cl] = make_float2(f2tff(p2), f2tff(p3));
            oacc[nt][0] *= al0; oacc[nt][1] *= al0;
            oacc[nt][2] *= al1; oacc[nt][3] *= al1;
        }
        ls0 += __shfl_xor_sync(0xffffffffu, ls0, 1);
        ls0 += __shfl_xor_sync(0xffffffffu, ls0, 2);
        ls1 += __shfl_xor_sync(0xffffffffu, ls1, 1);
        ls1 += __shfl_xor_sync(0xffffffffu, ls1, 2);
        l_i[0] = l_i[0] * al0 + ls0;
        l_i[1] = l_i[1] * al1 + ls1;

        __syncwarp();      // this warp's P rows written/read only by itself

        // O += P @ V  (warp: 16 x 64)
        #pragma unroll
        for (int ks = 0; ks < 8; ks++) {
            unsigned pa[4];
            ldsm4(pa, KP + (w * 16) * 68 + aoff + ks * 8);
            #pragma unroll
            for (int np = 0; np < 4; np++) {
                unsigned vb4[4];
                ldsm4(vb4, Vs + np * 16 * 68 + boff + ks * 8);
                mma8(oacc[2 * np],     pa, &vb4[0]);
                mma8(oacc[2 * np + 1], pa, &vb4[2]);
            }
        }
    }

    // normalize + write to concat layout [B*S, H*DK]
    const float inv0 = 1.f / l_i[0], inv1 = 1.f / l_i[1];
    const int b_ = bh / NH, h_ = bh % NH;
    const size_t mrow = (size_t)b_ * NS + q0 + w * 16 + g;
    #pragma unroll
    for (int nt = 0; nt < 8; nt++) {
        int cc = h_ * NDK + nt * 8 + 2 * tg;
        *(float2*)&g_cat[ mrow      * (NH * NDK) + cc] =
            make_float2(oacc[nt][0] * inv0, oacc[nt][1] * inv0);
        *(float2*)&g_cat[(mrow + 8) * (NH * NDK) + cc] =
            make_float2(oacc[nt][2] * inv1, oacc[nt][3] * inv1);
    }
}

// ---------------------------------------------------------------------------
// Kernel 3: output projection via tf32 MMA + ldmatrix.
// C[8192,1024] = g_cat @ Wo + bo. Block 128x128, 8 warps 4x2 -> warp 32x64.
// As [m][k] pitch 36; Bs [n][k] pitch 36 (transposed at store).
// ---------------------------------------------------------------------------
__global__ __launch_bounds__(256, 2) void proj_kernel(
    const float* __restrict__ Wo, const float* __restrict__ bo,
    float* __restrict__ out)
{
    __shared__ __align__(16) float As[128 * 36];
    __shared__ __align__(16) float Bs[128 * 36];

    const int m0 = blockIdx.y * 128;
    const int n0 = blockIdx.x * 128;
    const int tid  = threadIdx.x;
    const int warp = tid >> 5, lane = tid & 31;
    const int g = lane >> 2, tg = lane & 3;
    const int wm = warp >> 1, wn = warp & 1;

    const int aoff = (lane & 15) * 36 + (lane >> 4) * 4;
    const int boff = ((lane >> 4) * 8 + (lane & 7)) * 36 + ((lane >> 3) & 1) * 4;

    float acc[2][8][4] = {};
    const float* AsW = As + (wm * 32) * 36;
    const float* BsW = Bs + (wn * 64) * 36;

    for (int kk = 0; kk < ND; kk += 32) {
        // Stage A 128x32 row-major: 4 float4 per thread
        #pragma unroll
        for (int t = 0; t < 4; t++) {
            int f = tid + t * 256;
            int r = f >> 3, c4 = (f & 7) * 4;
            float4 v = *(const float4*)(g_cat + (size_t)(m0 + r) * ND + kk + c4);
            float4 w = make_float4(f2tff(v.x), f2tff(v.y), f2tff(v.z), f2tff(v.w));
            *(float4*)&As[r * 36 + c4] = w;
        }
        // Stage B 32x128 -> Bs[n][k]: 4 float4 per thread, staggered scatter
        #pragma unroll
        for (int t = 0; t < 4; t++) {
            int f = tid + t * 256;
            int r = f >> 5, c4 = (f & 31) * 4;
            float4 v = *(const float4*)(Wo + (size_t)(kk + r) * ND + n0 + c4);
            float vs[4] = {f2tff(v.x), f2tff(v.y), f2tff(v.z), f2tff(v.w)};
            #pragma unroll
            for (int i = 0; i < 4; i++) {
                int p = stag(i, tid);
                Bs[(c4 + p) * 36 + r] = vs[p];
            }
        }
        __syncthreads();

        #pragma unroll
        for (int ks = 0; ks < 4; ks++) {
            const int k0 = ks * 8;
            unsigned a[2][4];
            #pragma unroll
            for (int mt = 0; mt < 2; mt++)
                ldsm4(a[mt], AsW + mt * 16 * 36 + aoff + k0);
            #pragma unroll
            for (int np = 0; np < 4; np++) {
                unsigned b4[4];
                ldsm4(b4, BsW + np * 16 * 36 + boff + k0);
                #pragma unroll
                for (int mt = 0; mt < 2; mt++) {
                    mma8(acc[mt][2 * np],     a[mt], &b4[0]);
                    mma8(acc[mt][2 * np + 1], a[mt], &b4[2]);
                }
            }
        }
        __syncthreads();
    }

    // Epilogue
    #pragma unroll
    for (int nt = 0; nt < 8; nt++) {
        int cc = wn * 64 + nt * 8 + 2 * tg;
        float b0 = bo[n0 + cc], b1 = bo[n0 + cc + 1];
        #pragma unroll
        for (int mt = 0; mt < 2; mt++) {
            #pragma unroll
            for (int p = 0; p < 2; p++) {
                int rr = wm * 32 + mt * 16 + g + p * 8;
                float2 v;
                v.x = acc[mt][nt][2 * p + 0] + b0;
                v.y = acc[mt][nt][2 * p + 1] + b1;
                *(float2*)(out + (size_t)(m0 + rr) * ND + n0 + cc) = v;
            }
        }
    }
}

// ---------------------------------------------------------------------------
extern "C" void kernel_launch(void* const* d_in, const int* in_sizes, int n_in,
                              void* d_out, int out_size)
{
    (void)in_sizes; (void)n_in; (void)out_size;
    const float* x  = (const float*)d_in[0];
    // d_in[1] = encoder_output (unused in the self-attention path)
    const float* Wq = (const float*)d_in[2];
    const float* bq = (const float*)d_in[3];
    const float* Wk = (const float*)d_in[4];
    const float* bk = (const float*)d_in[5];
    const float* Wv = (const float*)d_in[6];
    const float* bv = (const float*)d_in[7];
    const float* Wo = (const float*)d_in[8];
    const float* bo = (const float*)d_in[9];
    float* out = (float*)d_out;

    qkv_kernel<<<dim3(NBS / 256, NH, 3), 256>>>(x, Wq, bq, Wk, bk, Wv, bv);
    attn_kernel<<<dim3(NS / 64, NB * NH), 128>>>();
    proj_kernel<<<dim3(ND / 128, NBS / 128), 256>>>(Wo, bo, out);
}

// round 9
// speedup vs baseline: 2.0723x; 1.1279x over previous
#include <cuda_runtime.h>
#include <cstddef>

// Problem constants
constexpr int NB  = 4;
constexpr int NS  = 2048;
constexpr int ND  = 1024;
constexpr int NH  = 16;
constexpr int NDK = 64;
constexpr int NBS = NB * NS;          // 8192

// Scratch (static device globals — no allocation)
__device__ float g_xr [(size_t)NBS * ND];                 // x, tf32-rounded
__device__ float g_wt [(size_t)NH * 3 * NDK * ND];        // [h][n=mat*64+c][k], tf32
__device__ float g_wot[(size_t)ND * ND];                  // Wo^T [n][k], tf32
__device__ float g_q  [(size_t)NB * NH * NS * NDK];       // [B,H,S,DK]  tf32-rounded
__device__ float g_k  [(size_t)NB * NH * NS * NDK];       // [B,H,S,DK]  tf32-rounded
__device__ float g_vt [(size_t)NB * NH * NDK * NS];       // [B,H,DK,S]  tf32-rounded
__device__ float g_cat[(size_t)NBS * NH * NDK];           // [B*S, H*DK] tf32-rounded

// ---------------------------------------------------------------------------
// helpers
// ---------------------------------------------------------------------------
__device__ __forceinline__ float f2tff(float f) {
    unsigned u;
    asm("cvt.rna.tf32.f32 %0, %1;" : "=r"(u) : "f"(f));
    return __uint_as_float(u);
}

// D += A(16x8,row) * B(8x8,col), tf32 inputs, fp32 accum
__device__ __forceinline__ void mma8(float* c, const unsigned* a, const unsigned* b) {
    asm volatile(
        "mma.sync.aligned.m16n8k8.row.col.f32.tf32.tf32.f32 "
        "{%0,%1,%2,%3}, {%4,%5,%6,%7}, {%8,%9}, {%0,%1,%2,%3};"
        : "+f"(c[0]), "+f"(c[1]), "+f"(c[2]), "+f"(c[3])
        : "r"(a[0]), "r"(a[1]), "r"(a[2]), "r"(a[3]), "r"(b[0]), "r"(b[1]));
}

// ldmatrix x4: four 8x8 b16 tiles == four 8x4 fp32 tiles, one per dest reg
__device__ __forceinline__ void ldsm4(unsigned* r, const float* p) {
    unsigned a = (unsigned)__cvta_generic_to_shared(p);
    asm volatile("ldmatrix.sync.aligned.m8n8.x4.shared.b16 {%0,%1,%2,%3}, [%4];"
        : "=r"(r[0]), "=r"(r[1]), "=r"(r[2]), "=r"(r[3]) : "r"(a));
}

// ---------------------------------------------------------------------------
// Prep kernels
// ---------------------------------------------------------------------------
__global__ void round_x_kernel(const float* __restrict__ x) {
    size_t i = ((size_t)blockIdx.x * 256 + threadIdx.x) * 4;
    float4 v = *(const float4*)(x + i);
    float4 w = make_float4(f2tff(v.x), f2tff(v.y), f2tff(v.z), f2tff(v.w));
    *(float4*)(g_xr + i) = w;
}

// Wq/Wk/Wv [H][1024][64] -> g_wt [h][mat*64+n][1024] (transposed, tf32)
__global__ void pack_w_kernel(const float* __restrict__ Wq,
                              const float* __restrict__ Wk,
                              const float* __restrict__ Wv) {
    __shared__ float t[32][33];
    int mat = blockIdx.z % 3, h = blockIdx.z / 3;
    const float* W = (mat == 0) ? Wq : (mat == 1) ? Wk : Wv;
    const float* src = W + (size_t)h * ND * NDK;
    int k0 = blockIdx.x * 32, n0 = blockIdx.y * 32;
    int tx = threadIdx.x, ty = threadIdx.y;
    #pragma unroll
    for (int i = 0; i < 4; i++)
        t[ty + 8 * i][tx] = src[(size_t)(k0 + ty + 8 * i) * NDK + n0 + tx];
    __syncthreads();
    float* dst = g_wt + ((size_t)h * 192 + mat * 64) * ND;
    #pragma unroll
    for (int i = 0; i < 4; i++)
        dst[(size_t)(n0 + ty + 8 * i) * ND + k0 + tx] = f2tff(t[tx][ty + 8 * i]);
}

// Wo [1024][1024] -> g_wot [n][k] = Wo[k][n], tf32
__global__ void pack_wo_kernel(const float* __restrict__ Wo) {
    __shared__ float t[32][33];
    int k0 = blockIdx.x * 32, n0 = blockIdx.y * 32;
    int tx = threadIdx.x, ty = threadIdx.y;
    #pragma unroll
    for (int i = 0; i < 4; i++)
        t[ty + 8 * i][tx] = Wo[(size_t)(k0 + ty + 8 * i) * ND + n0 + tx];
    __syncthreads();
    #pragma unroll
    for (int i = 0; i < 4; i++)
        g_wot[(size_t)(n0 + ty + 8 * i) * ND + k0 + tx] = f2tff(t[tx][ty + 8 * i]);
}

// ---------------------------------------------------------------------------
// Kernel 1: fused QKV projection, tf32 MMA + ldmatrix, pre-packed operands.
// Block tile 128(M) x 192(N = q|k|v) per head. 8 warps 4(m)x2(n) -> warp 32x96.
// As [m][k] pitch 36; Bs [n][k] pitch 36. No cvt / scatter in mainloop.
// ---------------------------------------------------------------------------
__global__ __launch_bounds__(256, 2) void qkv_kernel(
    const float* __restrict__ bq, const float* __restrict__ bk,
    const float* __restrict__ bv)
{
    __shared__ __align__(16) float As[128 * 36];
    __shared__ __align__(16) float Bs[192 * 36];

    const int h  = blockIdx.y;
    const int m0 = blockIdx.x * 128;
    const int tid  = threadIdx.x;
    const int warp = tid >> 5, lane = tid & 31;
    const int g = lane >> 2, tg = lane & 3;
    const int wm = warp >> 1, wn = warp & 1;   // 4 x 2 warps -> warp 32(m) x 96(n)

    const int aoff = (lane & 15) * 36 + (lane >> 4) * 4;
    const int boff = ((lane >> 4) * 8 + (lane & 7)) * 36 + ((lane >> 3) & 1) * 4;

    float acc[2][12][4] = {};
    const float* xb = g_xr + (size_t)m0 * ND;
    const float* wb = g_wt + (size_t)h * 192 * ND;
    const float* AsW = As + (wm * 32) * 36;
    const float* BsW = Bs + (wn * 96) * 36;

    for (int kk = 0; kk < ND; kk += 32) {
        // A 128x32: 4 float4 per thread
        #pragma unroll
        for (int t = 0; t < 4; t++) {
            int f = tid + t * 256;
            int r = f >> 3, c4 = (f & 7) * 4;
            *(float4*)&As[r * 36 + c4] = *(const float4*)(xb + (size_t)r * ND + kk + c4);
        }
        // B 192x32: 6 float4 per thread
        #pragma unroll
        for (int t = 0; t < 6; t++) {
            int f = tid + t * 256;
            int r = f >> 3, c4 = (f & 7) * 4;
            *(float4*)&Bs[r * 36 + c4] = *(const float4*)(wb + (size_t)r * ND + kk + c4);
        }
        __syncthreads();

        #pragma unroll
        for (int ks = 0; ks < 4; ks++) {
            const int k0 = ks * 8;
            unsigned a[2][4];
            ldsm4(a[0], AsW + aoff + k0);
            ldsm4(a[1], AsW + 16 * 36 + aoff + k0);
            #pragma unroll
            for (int np = 0; np < 6; np++) {
                unsigned b4[4];
                ldsm4(b4, BsW + np * 16 * 36 + boff + k0);
                mma8(acc[0][2 * np],     a[0], &b4[0]);
                mma8(acc[0][2 * np + 1], a[0], &b4[2]);
                mma8(acc[1][2 * np],     a[1], &b4[0]);
                mma8(acc[1][2 * np + 1], a[1], &b4[2]);
            }
        }
        __syncthreads();
    }

    // Epilogue: + bias, tf32-round, route q/k row-major, v transposed
    const int b_ = m0 / NS, s0 = m0 % NS;
    const int bh = b_ * NH + h;
    #pragma unroll
    for (int nt = 0; nt < 12; nt++) {
        int n_g = wn * 96 + nt * 8 + 2 * tg;
        int mat = n_g >> 6, cm = n_g & 63;
        const float* bp = (mat == 0) ? bq : (mat == 1) ? bk : bv;
        float b0v = bp[h * NDK + cm], b1v = bp[h * NDK + cm + 1];
        if (mat < 2) {
            float* dst = ((mat == 0) ? g_q : g_k) + (size_t)bh * NS * NDK;
            #pragma unroll
            for (int mt = 0; mt < 2; mt++)
                #pragma unroll
                for (int p = 0; p < 2; p++) {
                    int rr = wm * 32 + mt * 16 + g + p * 8;
                    float2 v;
                    v.x = f2tff(acc[mt][nt][2 * p + 0] + b0v);
                    v.y = f2tff(acc[mt][nt][2 * p + 1] + b1v);
                    *(float2*)(dst + (size_t)(s0 + rr) * NDK + cm) = v;
                }
        } else {
            float* vt = g_vt + (size_t)bh * NDK * NS;
            #pragma unroll
            for (int mt = 0; mt < 2; mt++)
                #pragma unroll
                for (int p = 0; p < 2; p++) {
                    int rr = wm * 32 + mt * 16 + g + p * 8;
                    int s = s0 + rr;
                    vt[(size_t)cm       * NS + s] = f2tff(acc[mt][nt][2 * p + 0] + b0v);
                    vt[(size_t)(cm + 1) * NS + s] = f2tff(acc[mt][nt][2 * p + 1] + b1v);
                }
        }
    }
}

// ---------------------------------------------------------------------------
// Kernel 2: causal flash attention, tf32 MMA + ldmatrix, pre-rounded inputs.
// 128 threads (4 warps). Q tile 64 rows (16/warp, Q frags in regs), key tile 64.
// KP [row][feat] pitch 68 holds Q, then K, then P. Vs [feat][key] pitch 68.
// ---------------------------------------------------------------------------
__global__ __launch_bounds__(128) void attn_kernel()
{
    __shared__ __align__(16) float KP[64 * 68];
    __shared__ __align__(16) float Vs[64 * 68];

    const int qt = (int)(gridDim.x - 1) - (int)blockIdx.x;  // heavy first
    const int bh = blockIdx.y;
    const int q0 = qt * 64;
    const float* qb  = g_q  + (size_t)bh * NS * NDK;
    const float* kb  = g_k  + (size_t)bh * NS * NDK;
    const float* vtb = g_vt + (size_t)bh * NDK * NS;

    const int tid = threadIdx.x;
    const int w = tid >> 5, lane = tid & 31;
    const int g = lane >> 2, tg = lane & 3;

    const int aoff = (lane & 15) * 68 + (lane >> 4) * 4;
    const int boff = ((lane >> 4) * 8 + (lane & 7)) * 68 + ((lane >> 3) & 1) * 4;

    // Stage Q tile (pre-rounded) row-major
    #pragma unroll
    for (int t = 0; t < 8; t++) {
        int f = tid + t * 128;
        int r = f >> 4, c4 = (f & 15) * 4;
        *(float4*)&KP[r * 68 + c4] = *(const float4*)(qb + (size_t)(q0 + r) * NDK + c4);
    }
    __syncthreads();

    // Q fragments for all 8 k-steps
    unsigned qa[8][4];
    #pragma unroll
    for (int ks = 0; ks < 8; ks++)
        ldsm4(qa[ks], KP + (w * 16) * 68 + aoff + ks * 8);

    float oacc[8][4] = {};
    float m_i[2] = {-3.0e38f, -3.0e38f};
    float l_i[2] = {0.f, 0.f};

    for (int jt = 0; jt <= qt; jt++) {
        __syncthreads();   // prior-iter KP/Vs reads (and qa loads) complete
        const int kc0 = jt * 64;
        // K tile 64x64 row-major into KP
        #pragma unroll
        for (int t = 0; t < 8; t++) {
            int f = tid + t * 128;
            int r = f >> 4, c4 = (f & 15) * 4;
            *(float4*)&KP[r * 68 + c4] = *(const float4*)(kb + (size_t)(kc0 + r) * NDK + c4);
        }
        // V tile [feat][key] straight from transposed g_vt
        #pragma unroll
        for (int t = 0; t < 8; t++) {
            int f = tid + t * 128;
            int r = f >> 4, c4 = (f & 15) * 4;
            *(float4*)&Vs[r * 68 + c4] = *(const float4*)(vtb + (size_t)r * NS + kc0 + c4);
        }
        __syncthreads();

        // S = Q K^T  (warp: 16 x 64)
        float sacc[8][4] = {};
        #pragma unroll
        for (int ks = 0; ks < 8; ks++) {
            #pragma unroll
            for (int np = 0; np < 4; np++) {
                unsigned kb4[4];
                ldsm4(kb4, KP + np * 16 * 68 + boff + ks * 8);
                mma8(sacc[2 * np],     qa[ks], &kb4[0]);
                mma8(sacc[2 * np + 1], qa[ks], &kb4[2]);
            }
        }
        __syncthreads();   // all S reads of KP done before P overwrite

        // scale + causal mask
        const int r0 = q0 + w * 16 + g;
        if (jt == qt) {
            #pragma unroll
            for (int nt = 0; nt < 8; nt++) {
                int col = kc0 + nt * 8 + 2 * tg;
                sacc[nt][0] = (col     <= r0    ) ? sacc[nt][0] * 0.125f : -3.0e38f;
                sacc[nt][1] = (col + 1 <= r0    ) ? sacc[nt][1] * 0.125f : -3.0e38f;
                sacc[nt][2] = (col     <= r0 + 8) ? sacc[nt][2] * 0.125f : -3.0e38f;
                sacc[nt][3] = (col + 1 <= r0 + 8) ? sacc[nt][3] * 0.125f : -3.0e38f;
            }
        } else {
            #pragma unroll
            for (int nt = 0; nt < 8; nt++) {
                sacc[nt][0] *= 0.125f; sacc[nt][1] *= 0.125f;
                sacc[nt][2] *= 0.125f; sacc[nt][3] *= 0.125f;
            }
        }

        // row max
        float mt0 = -3.0e38f, mt1 = -3.0e38f;
        #pragma unroll
        for (int nt = 0; nt < 8; nt++) {
            mt0 = fmaxf(mt0, fmaxf(sacc[nt][0], sacc[nt][1]));
            mt1 = fmaxf(mt1, fmaxf(sacc[nt][2], sacc[nt][3]));
        }
        mt0 = fmaxf(mt0, __shfl_xor_sync(0xffffffffu, mt0, 1));
        mt0 = fmaxf(mt0, __shfl_xor_sync(0xffffffffu, mt0, 2));
        mt1 = fmaxf(mt1, __shfl_xor_sync(0xffffffffu, mt1, 1));
        mt1 = fmaxf(mt1, __shfl_xor_sync(0xffffffffu, mt1, 2));

        float mn0 = fmaxf(m_i[0], mt0), mn1 = fmaxf(m_i[1], mt1);
        float al0 = __expf(m_i[0] - mn0), al1 = __expf(m_i[1] - mn1);
        m_i[0] = mn0; m_i[1] = mn1;

        const int rb0 = (w * 16 + g) * 68;
        const int rb1 = rb0 + 8 * 68;
        float ls0 = 0.f, ls1 = 0.f;
        #pragma unroll
        for (int nt = 0; nt < 8; nt++) {
            float p0 = __expf(sacc[nt][0] - mn0);
            float p1 = __expf(sacc[nt][1] - mn0);
            float p2 = __expf(sacc[nt][2] - mn1);
            float p3 = __expf(sacc[nt][3] - mn1);
            ls0 += p0 + p1; ls1 += p2 + p3;
            int cl = nt * 8 + 2 * tg;
            *(float2*)&KP[rb0 + cl] = make_float2(f2tff(p0), f2tff(p1));
            *(float2*)&KP[rb1 + cl] = make_float2(f2tff(p2), f2tff(p3));
            oacc[nt][0] *= al0; oacc[nt][1] *= al0;
            oacc[nt][2] *= al1; oacc[nt][3] *= al1;
        }
        ls0 += __shfl_xor_sync(0xffffffffu, ls0, 1);
        ls0 += __shfl_xor_sync(0xffffffffu, ls0, 2);
        ls1 += __shfl_xor_sync(0xffffffffu, ls1, 1);
        ls1 += __shfl_xor_sync(0xffffffffu, ls1, 2);
        l_i[0] = l_i[0] * al0 + ls0;
        l_i[1] = l_i[1] * al1 + ls1;

        __syncwarp();      // this warp's P rows written/read only by itself

        // O += P @ V  (warp: 16 x 64)
        #pragma unroll
        for (int ks = 0; ks < 8; ks++) {
            unsigned pa[4];
            ldsm4(pa, KP + (w * 16) * 68 + aoff + ks * 8);
            #pragma unroll
            for (int np = 0; np < 4; np++) {
                unsigned vb4[4];
                ldsm4(vb4, Vs + np * 16 * 68 + boff + ks * 8);
                mma8(oacc[2 * np],     pa, &vb4[0]);
                mma8(oacc[2 * np + 1], pa, &vb4[2]);
            }
        }
    }

    // normalize + tf32-round + write to concat layout [B*S, H*DK]
    const float inv0 = 1.f / l_i[0], inv1 = 1.f / l_i[1];
    const int b_ = bh / NH, h_ = bh % NH;
    const size_t mrow = (size_t)b_ * NS + q0 + w * 16 + g;
    #pragma unroll
    for (int nt = 0; nt < 8; nt++) {
        int cc = h_ * NDK + nt * 8 + 2 * tg;
        *(float2*)&g_cat[ mrow      * (NH * NDK) + cc] =
            make_float2(f2tff(oacc[nt][0] * inv0), f2tff(oacc[nt][1] * inv0));
        *(float2*)&g_cat[(mrow + 8) * (NH * NDK) + cc] =
            make_float2(f2tff(oacc[nt][2] * inv1), f2tff(oacc[nt][3] * inv1));
    }
}

// ---------------------------------------------------------------------------
// Kernel 3: output projection, tf32 MMA + ldmatrix, pre-packed operands.
// C[8192,1024] = g_cat @ Wo + bo. Block 128x128, 8 warps 4x2 -> warp 32x64.
// ---------------------------------------------------------------------------
__global__ __launch_bounds__(256, 2) void proj_kernel(
    const float* __restrict__ bo, float* __restrict__ out)
{
    __shared__ __align__(16) float As[128 * 36];
    __shared__ __align__(16) float Bs[128 * 36];

    const int m0 = blockIdx.y * 128;
    const int n0 = blockIdx.x * 128;
    const int tid  = threadIdx.x;
    const int warp = tid >> 5, lane = tid & 31;
    const int g = lane >> 2, tg = lane & 3;
    const int wm = warp >> 1, wn = warp & 1;

    const int aoff = (lane & 15) * 36 + (lane >> 4) * 4;
    const int boff = ((lane >> 4) * 8 + (lane & 7)) * 36 + ((lane >> 3) & 1) * 4;

    float acc[2][8][4] = {};
    const float* AsW = As + (wm * 32) * 36;
    const float* BsW = Bs + (wn * 64) * 36;

    for (int kk = 0; kk < ND; kk += 32) {
        // A 128x32 from pre-rounded g_cat
        #pragma unroll
        for (int t = 0; t < 4; t++) {
            int f = tid + t * 256;
            int r = f >> 3, c4 = (f & 7) * 4;
            *(float4*)&As[r * 36 + c4] =
                *(const float4*)(g_cat + (size_t)(m0 + r) * ND + kk + c4);
        }
        // B 128x32 from packed Wo^T [n][k]
        #pragma unroll
        for (int t = 0; t < 4; t++) {
            int f = tid + t * 256;
            int r = f >> 3, c4 = (f & 7) * 4;
            *(float4*)&Bs[r * 36 + c4] =
                *(const float4*)(g_wot + (size_t)(n0 + r) * ND + kk + c4);
        }
        __syncthreads();

        #pragma unroll
        for (int ks = 0; ks < 4; ks++) {
            const int k0 = ks * 8;
            unsigned a[2][4];
            ldsm4(a[0], AsW + aoff + k0);
            ldsm4(a[1], AsW + 16 * 36 + aoff + k0);
            #pragma unroll
            for (int np = 0; np < 4; np++) {
                unsigned b4[4];
                ldsm4(b4, BsW + np * 16 * 36 + boff + k0);
                mma8(acc[0][2 * np],     a[0], &b4[0]);
                mma8(acc[0][2 * np + 1], a[0], &b4[2]);
                mma8(acc[1][2 * np],     a[1], &b4[0]);
                mma8(acc[1][2 * np + 1], a[1], &b4[2]);
            }
        }
        __syncthreads();
    }

    // Epilogue (final output stays fp32, no rounding)
    #pragma unroll
    for (int nt = 0; nt < 8; nt++) {
        int cc = wn * 64 + nt * 8 + 2 * tg;
        float b0 = bo[n0 + cc], b1 = bo[n0 + cc + 1];
        #pragma unroll
        for (int mt = 0; mt < 2; mt++)
            #pragma unroll
            for (int p = 0; p < 2; p++) {
                int rr = wm * 32 + mt * 16 + g + p * 8;
                float2 v;
                v.x = acc[mt][nt][2 * p + 0] + b0;
                v.y = acc[mt][nt][2 * p + 1] + b1;
                *(float2*)(out + (size_t)(m0 + rr) * ND + n0 + cc) = v;
            }
    }
}

// ---------------------------------------------------------------------------
extern "C" void kernel_launch(void* const* d_in, const int* in_sizes, int n_in,
                              void* d_out, int out_size)
{
    (void)in_sizes; (void)n_in; (void)out_size;
    const float* x  = (const float*)d_in[0];
    // d_in[1] = encoder_output (unused in the self-attention path)
    const float* Wq = (const float*)d_in[2];
    const float* bq = (const float*)d_in[3];
    const float* Wk = (const float*)d_in[4];
    const float* bk = (const float*)d_in[5];
    const float* Wv = (const float*)d_in[6];
    const float* bv = (const float*)d_in[7];
    const float* Wo = (const float*)d_in[8];
    const float* bo = (const float*)d_in[9];
    float* out = (float*)d_out;

    round_x_kernel<<<(NBS * ND) / (256 * 4), 256>>>(x);
    pack_w_kernel<<<dim3(ND / 32, NDK / 32, NH * 3), dim3(32, 8)>>>(Wq, Wk, Wv);
    pack_wo_kernel<<<dim3(ND / 32, ND / 32), dim3(32, 8)>>>(Wo);
    qkv_kernel<<<dim3(NBS / 128, NH), 256>>>(bq, bk, bv);
    attn_kernel<<<dim3(NS / 64, NB * NH), 128>>>();
    proj_kernel<<<dim3(ND / 128, NBS / 128), 256>>>(bo, out);
}

// round 10
// speedup vs baseline: 2.2290x; 1.0756x over previous
#include <cuda_runtime.h>
#include <cstddef>

// Problem constants
constexpr int NB  = 4;
constexpr int NS  = 2048;
constexpr int ND  = 1024;
constexpr int NH  = 16;
constexpr int NDK = 64;
constexpr int NBS = NB * NS;          // 8192

// Scratch (static device globals — no allocation)
__device__ float g_xr [(size_t)NBS * ND];                 // x, tf32-rounded
__device__ float g_wt [(size_t)NH * 3 * NDK * ND];        // [h*192+n][k], tf32
__device__ float g_wot[(size_t)ND * ND];                  // Wo^T [n][k], tf32
__device__ float g_q  [(size_t)NB * NH * NS * NDK];       // [B,H,S,DK]  tf32-rounded
__device__ float g_k  [(size_t)NB * NH * NS * NDK];       // [B,H,S,DK]  tf32-rounded
__device__ float g_vt [(size_t)NB * NH * NDK * NS];       // [B,H,DK,S]  tf32-rounded
__device__ float g_cat[(size_t)NBS * NH * NDK];           // [B*S, H*DK] tf32-rounded

// ---------------------------------------------------------------------------
// helpers
// ---------------------------------------------------------------------------
__device__ __forceinline__ float f2tff(float f) {
    unsigned u;
    asm("cvt.rna.tf32.f32 %0, %1;" : "=r"(u) : "f"(f));
    return __uint_as_float(u);
}

__device__ __forceinline__ void mma8(float* c, const unsigned* a, const unsigned* b) {
    asm volatile(
        "mma.sync.aligned.m16n8k8.row.col.f32.tf32.tf32.f32 "
        "{%0,%1,%2,%3}, {%4,%5,%6,%7}, {%8,%9}, {%0,%1,%2,%3};"
        : "+f"(c[0]), "+f"(c[1]), "+f"(c[2]), "+f"(c[3])
        : "r"(a[0]), "r"(a[1]), "r"(a[2]), "r"(a[3]), "r"(b[0]), "r"(b[1]));
}

__device__ __forceinline__ void ldsm4(unsigned* r, const float* p) {
    unsigned a = (unsigned)__cvta_generic_to_shared(p);
    asm volatile("ldmatrix.sync.aligned.m8n8.x4.shared.b16 {%0,%1,%2,%3}, [%4];"
        : "=r"(r[0]), "=r"(r[1]), "=r"(r[2]), "=r"(r[3]) : "r"(a));
}

__device__ __forceinline__ void cpa16(float* dst, const float* src) {
    unsigned d = (unsigned)__cvta_generic_to_shared(dst);
    asm volatile("cp.async.cg.shared.global [%0], [%1], 16;" :: "r"(d), "l"(src));
}
#define CP_COMMIT() asm volatile("cp.async.commit_group;")
#define CP_WAIT0()  asm volatile("cp.async.wait_group 0;")

// ---------------------------------------------------------------------------
// Prep kernels
// ---------------------------------------------------------------------------
__global__ void round_x_kernel(const float* __restrict__ x) {
    size_t i = ((size_t)blockIdx.x * 256 + threadIdx.x) * 4;
    float4 v = *(const float4*)(x + i);
    *(float4*)(g_xr + i) =
        make_float4(f2tff(v.x), f2tff(v.y), f2tff(v.z), f2tff(v.w));
}

// Wq/Wk/Wv [H][1024][64] -> g_wt [h*192 + mat*64 + n][1024] (transposed, tf32)
__global__ void pack_w_kernel(const float* __restrict__ Wq,
                              const float* __restrict__ Wk,
                              const float* __restrict__ Wv) {
    __shared__ float t[32][33];
    int mat = blockIdx.z % 3, h = blockIdx.z / 3;
    const float* W = (mat == 0) ? Wq : (mat == 1) ? Wk : Wv;
    const float* src = W + (size_t)h * ND * NDK;
    int k0 = blockIdx.x * 32, n0 = blockIdx.y * 32;
    int tx = threadIdx.x, ty = threadIdx.y;
    #pragma unroll
    for (int i = 0; i < 4; i++)
        t[ty + 8 * i][tx] = src[(size_t)(k0 + ty + 8 * i) * NDK + n0 + tx];
    __syncthreads();
    float* dst = g_wt + ((size_t)h * 192 + mat * 64) * ND;
    #pragma unroll
    for (int i = 0; i < 4; i++)
        dst[(size_t)(n0 + ty + 8 * i) * ND + k0 + tx] = f2tff(t[tx][ty + 8 * i]);
}

__global__ void pack_wo_kernel(const float* __restrict__ Wo) {
    __shared__ float t[32][33];
    int k0 = blockIdx.x * 32, n0 = blockIdx.y * 32;
    int tx = threadIdx.x, ty = threadIdx.y;
    #pragma unroll
    for (int i = 0; i < 4; i++)
        t[ty + 8 * i][tx] = Wo[(size_t)(k0 + ty + 8 * i) * ND + n0 + tx];
    __syncthreads();
    #pragma unroll
    for (int i = 0; i < 4; i++)
        g_wot[(size_t)(n0 + ty + 8 * i) * ND + k0 + tx] = f2tff(t[tx][ty + 8 * i]);
}

// ---------------------------------------------------------------------------
// Kernel 1: fused QKV projection. C[8192, 3072] = xr @ g_wt^T (+bias routing).
// Block 128(M) x 128(N), BK=16, 2-stage cp.async pipeline, 1 barrier/iter.
// 8 warps 4(m)x2(n) -> warp 32x64. Pitch 20.
// ---------------------------------------------------------------------------
__global__ __launch_bounds__(256, 2) void qkv_kernel(
    const float* __restrict__ bq, const float* __restrict__ bk,
    const float* __restrict__ bv)
{
    __shared__ __align__(16) float As[2 * 128 * 20];
    __shared__ __align__(16) float Bs[2 * 128 * 20];

    const int m0 = blockIdx.x * 128;
    const int n0 = blockIdx.y * 128;
    const int tid  = threadIdx.x;
    const int warp = tid >> 5, lane = tid & 31;
    const int g = lane >> 2, tg = lane & 3;
    const int wm = warp >> 1, wn = warp & 1;

    const int aoff = (lane & 15) * 20 + (lane >> 4) * 4;
    const int boff = ((lane >> 4) * 8 + (lane & 7)) * 20 + ((lane >> 3) & 1) * 4;

    const float* xb = g_xr + (size_t)m0 * ND;
    const float* wb = g_wt + (size_t)n0 * ND;

    const int sr = tid >> 2, sc = (tid & 3) * 4;   // staging row/col (2 f4 each)

    float acc[2][8][4] = {};

    // stage 0
    {
        cpa16(&As[sr * 20 + sc],        xb + (size_t)sr * ND + sc);
        cpa16(&As[(sr + 64) * 20 + sc], xb + (size_t)(sr + 64) * ND + sc);
        cpa16(&Bs[sr * 20 + sc],        wb + (size_t)sr * ND + sc);
        cpa16(&Bs[(sr + 64) * 20 + sc], wb + (size_t)(sr + 64) * ND + sc);
    }
    CP_COMMIT();

    for (int i = 0; i < 64; i++) {
        CP_WAIT0();
        __syncthreads();
        if (i < 63) {
            int buf = ((i + 1) & 1) * (128 * 20);
            int kk = (i + 1) * 16;
            cpa16(&As[buf + sr * 20 + sc],        xb + (size_t)sr * ND + kk + sc);
            cpa16(&As[buf + (sr + 64) * 20 + sc], xb + (size_t)(sr + 64) * ND + kk + sc);
            cpa16(&Bs[buf + sr * 20 + sc],        wb + (size_t)sr * ND + kk + sc);
            cpa16(&Bs[buf + (sr + 64) * 20 + sc], wb + (size_t)(sr + 64) * ND + kk + sc);
            CP_COMMIT();
        }
        const float* AsW = As + (i & 1) * (128 * 20) + (wm * 32) * 20;
        const float* BsW = Bs + (i & 1) * (128 * 20) + (wn * 64) * 20;
        #pragma unroll
        for (int ks = 0; ks < 2; ks++) {
            unsigned a[2][4];
            ldsm4(a[0], AsW + aoff + ks * 8);
            ldsm4(a[1], AsW + 16 * 20 + aoff + ks * 8);
            #pragma unroll
            for (int np = 0; np < 4; np++) {
                unsigned b4[4];
                ldsm4(b4, BsW + np * 16 * 20 + boff + ks * 8);
                mma8(acc[0][2 * np],     a[0], &b4[0]);
                mma8(acc[0][2 * np + 1], a[0], &b4[2]);
                mma8(acc[1][2 * np],     a[1], &b4[0]);
                mma8(acc[1][2 * np + 1], a[1], &b4[2]);
            }
        }
    }

    // Epilogue: + bias, tf32-round, route q/k row-major, v transposed
    #pragma unroll
    for (int nt = 0; nt < 8; nt++) {
        int n_g = n0 + wn * 64 + nt * 8 + 2 * tg;
        int h = n_g / 192, wh = n_g % 192;
        int mat = wh >> 6, cm = wh & 63;
        const float* bp = (mat == 0) ? bq : (mat == 1) ? bk : bv;
        float b0v = bp[h * NDK + cm], b1v = bp[h * NDK + cm + 1];
        #pragma unroll
        for (int mt = 0; mt < 2; mt++)
            #pragma unroll
            for (int p = 0; p < 2; p++) {
                int m = m0 + wm * 32 + mt * 16 + g + p * 8;
                int b_ = m >> 11, s = m & 2047;
                int bh = b_ * NH + h;
                float v0 = f2tff(acc[mt][nt][2 * p + 0] + b0v);
                float v1 = f2tff(acc[mt][nt][2 * p + 1] + b1v);
                if (mat < 2) {
                    float* dst = ((mat == 0) ? g_q : g_k) + (size_t)bh * NS * NDK;
                    *(float2*)(dst + (size_t)s * NDK + cm) = make_float2(v0, v1);
                } else {
                    float* vt = g_vt + (size_t)bh * NDK * NS;
                    vt[(size_t)cm       * NS + s] = v0;
                    vt[(size_t)(cm + 1) * NS + s] = v1;
                }
            }
    }
}

// ---------------------------------------------------------------------------
// Kernel 2: causal flash attention, 32-key tiles, 2-stage cp.async pipeline.
// 128 threads (4 warps). Q tile 64 rows (frags in regs). 1 barrier/KV tile.
// Kb: 2x(32 keys x 64 feat) pitch 68. Vb: 2x(64 feat x 32 keys) pitch 36.
// Pb: 64 q x 32 keys pitch 36 (warp-private rows -> no block sync needed).
// ---------------------------------------------------------------------------
__global__ __launch_bounds__(128) void attn_kernel()
{
    __shared__ __align__(16) float Kb[2 * 32 * 68];   // also initial Q staging (64x68)
    __shared__ __align__(16) float Vb[2 * 64 * 36];
    __shared__ __align__(16) float Pb[64 * 36];

    const int qt = (int)(gridDim.x - 1) - (int)blockIdx.x;  // heavy first
    const int bh = blockIdx.y;
    const int q0 = qt * 64;
    const float* qb  = g_q  + (size_t)bh * NS * NDK;
    const float* kb  = g_k  + (size_t)bh * NS * NDK;
    const float* vtb = g_vt + (size_t)bh * NDK * NS;

    const int tid = threadIdx.x;
    const int w = tid >> 5, lane = tid & 31;
    const int g = lane >> 2, tg = lane & 3;

    const int aoff68 = (lane & 15) * 68 + (lane >> 4) * 4;
    const int boff68 = ((lane >> 4) * 8 + (lane & 7)) * 68 + ((lane >> 3) & 1) * 4;
    const int aoff36 = (lane & 15) * 36 + (lane >> 4) * 4;
    const int boff36 = ((lane >> 4) * 8 + (lane & 7)) * 36 + ((lane >> 3) & 1) * 4;

    // Stage Q 64x64 into Kb (contiguous 64 rows, pitch 68)
    #pragma unroll
    for (int t = 0; t < 8; t++) {
        int f = tid + t * 128;
        int r = f >> 4, c4 = (f & 15) * 4;
        *(float4*)&Kb[r * 68 + c4] = *(const float4*)(qb + (size_t)(q0 + r) * NDK + c4);
    }
    __syncthreads();
    unsigned qa[8][4];
    #pragma unroll
    for (int ks = 0; ks < 8; ks++)
        ldsm4(qa[ks], Kb + (w * 16) * 68 + aoff68 + ks * 8);
    __syncthreads();   // all qa loads done before cp.async overwrites Kb

    const int kr = tid >> 2, kc = (tid & 3) * 4;   // K staging: 32 rows x 64, 4 f4/thr... (2 rows each)
    const int vr = tid >> 1, vc = (tid & 1) * 16;  // unused helper
    (void)vr; (void)vc;

    // preload KV tile 0
    {
        #pragma unroll
        for (int t = 0; t < 4; t++) {
            int f = tid + t * 128;
            int r = f >> 4, c4 = (f & 15) * 4;
            cpa16(&Kb[r * 68 + c4], kb + (size_t)r * NDK + c4);
        }
        #pragma unroll
        for (int t = 0; t < 4; t++) {
            int f = tid + t * 128;
            int r = f >> 3, c4 = (f & 7) * 4;
            cpa16(&Vb[r * 36 + c4], vtb + (size_t)r * NS + c4);
        }
    }
    CP_COMMIT();
    (void)kr; (void)kc;

    float oacc[8][4] = {};
    float m_i[2] = {-3.0e38f, -3.0e38f};
    float l_i[2] = {0.f, 0.f};

    const int nkt = 2 * qt + 2;
    for (int jt = 0; jt < nkt; jt++) {
        CP_WAIT0();
        __syncthreads();   // tile jt landed; all warps done with tile jt-1
        if (jt + 1 < nkt) {
            int kbuf = ((jt + 1) & 1) * (32 * 68);
            int vbuf = ((jt + 1) & 1) * (64 * 36);
            int kc0n = (jt + 1) * 32;
            #pragma unroll
            for (int t = 0; t < 4; t++) {
                int f = tid + t * 128;
                int r = f >> 4, c4 = (f & 15) * 4;
                cpa16(&Kb[kbuf + r * 68 + c4], kb + (size_t)(kc0n + r) * NDK + c4);
            }
            #pragma unroll
            for (int t = 0; t < 4; t++) {
                int f = tid + t * 128;
                int r = f >> 3, c4 = (f & 7) * 4;
                cpa16(&Vb[vbuf + r * 36 + c4], vtb + (size_t)r * NS + kc0n + c4);
            }
            CP_COMMIT();
        }
        const float* Kt = Kb + (jt & 1) * (32 * 68);
        const float* Vt = Vb + (jt & 1) * (64 * 36);
        const int kc0 = jt * 32;

        // S = Q K^T  (warp: 16 x 32)
        float sacc[4][4] = {};
        #pragma unroll
        for (int ks = 0; ks < 8; ks++) {
            #pragma unroll
            for (int np = 0; np < 2; np++) {
                unsigned kb4[4];
                ldsm4(kb4, Kt + np * 16 * 68 + boff68 + ks * 8);
                mma8(sacc[2 * np],     qa[ks], &kb4[0]);
                mma8(sacc[2 * np + 1], qa[ks], &kb4[2]);
            }
        }

        // scale + causal mask (only last two tiles touch the diagonal)
        const int r0 = q0 + w * 16 + g;
        if (jt >= nkt - 2) {
            #pragma unroll
            for (int nt = 0; nt < 4; nt++) {
                int col = kc0 + nt * 8 + 2 * tg;
                sacc[nt][0] = (col     <= r0    ) ? sacc[nt][0] * 0.125f : -3.0e38f;
                sacc[nt][1] = (col + 1 <= r0    ) ? sacc[nt][1] * 0.125f : -3.0e38f;
                sacc[nt][2] = (col     <= r0 + 8) ? sacc[nt][2] * 0.125f : -3.0e38f;
                sacc[nt][3] = (col + 1 <= r0 + 8) ? sacc[nt][3] * 0.125f : -3.0e38f;
            }
        } else {
            #pragma unroll
            for (int nt = 0; nt < 4; nt++) {
                sacc[nt][0] *= 0.125f; sacc[nt][1] *= 0.125f;
                sacc[nt][2] *= 0.125f; sacc[nt][3] *= 0.125f;
            }
        }

        // row max
        float mt0 = -3.0e38f, mt1 = -3.0e38f;
        #pragma unroll
        for (int nt = 0; nt < 4; nt++) {
            mt0 = fmaxf(mt0, fmaxf(sacc[nt][0], sacc[nt][1]));
            mt1 = fmaxf(mt1, fmaxf(sacc[nt][2], sacc[nt][3]));
        }
        mt0 = fmaxf(mt0, __shfl_xor_sync(0xffffffffu, mt0, 1));
        mt0 = fmaxf(mt0, __shfl_xor_sync(0xffffffffu, mt0, 2));
        mt1 = fmaxf(mt1, __shfl_xor_sync(0xffffffffu, mt1, 1));
        mt1 = fmaxf(mt1, __shfl_xor_sync(0xffffffffu, mt1, 2));

        float mn0 = fmaxf(m_i[0], mt0), mn1 = fmaxf(m_i[1], mt1);
        float al0 = __expf(m_i[0] - mn0), al1 = __expf(m_i[1] - mn1);
        m_i[0] = mn0; m_i[1] = mn1;

        const int rb0 = (w * 16 + g) * 36;
        const int rb1 = rb0 + 8 * 36;
        float ls0 = 0.f, ls1 = 0.f;
        #pragma unroll
        for (int nt = 0; nt < 4; nt++) {
            float p0 = __expf(sacc[nt][0] - mn0);
            float p1 = __expf(sacc[nt][1] - mn0);
            float p2 = __expf(sacc[nt][2] - mn1);
            float p3 = __expf(sacc[nt][3] - mn1);
            ls0 += p0 + p1; ls1 += p2 + p3;
            int cl = nt * 8 + 2 * tg;
            *(float2*)&Pb[rb0 + cl] = make_float2(f2tff(p0), f2tff(p1));
            *(float2*)&Pb[rb1 + cl] = make_float2(f2tff(p2), f2tff(p3));
        }
        #pragma unroll
        for (int nt = 0; nt < 8; nt++) {
            oacc[nt][0] *= al0; oacc[nt][1] *= al0;
            oacc[nt][2] *= al1; oacc[nt][3] *= al1;
        }
        ls0 += __shfl_xor_sync(0xffffffffu, ls0, 1);
        ls0 += __shfl_xor_sync(0xffffffffu, ls0, 2);
        ls1 += __shfl_xor_sync(0xffffffffu, ls1, 1);
        ls1 += __shfl_xor_sync(0xffffffffu, ls1, 2);
        l_i[0] = l_i[0] * al0 + ls0;
        l_i[1] = l_i[1] * al1 + ls1;

        __syncwarp();      // P rows warp-private: warp-level fence suffices

        // O += P @ V  (warp: 16 x 64, k = 32 keys)
        #pragma unroll
        for (int ks = 0; ks < 4; ks++) {
            unsigned pa[4];
            ldsm4(pa, Pb + (w * 16) * 36 + aoff36 + ks * 8);
            #pragma unroll
            for (int np = 0; np < 4; np++) {
                unsigned vb4[4];
                ldsm4(vb4, Vt + np * 16 * 36 + boff36 + ks * 8);
                mma8(oacc[2 * np],     pa, &vb4[0]);
                mma8(oacc[2 * np + 1], pa, &vb4[2]);
            }
        }
    }

    // normalize + tf32-round + write concat layout [B*S, H*DK]
    const float inv0 = 1.f / l_i[0], inv1 = 1.f / l_i[1];
    const int b_ = bh / NH, h_ = bh % NH;
    const size_t mrow = (size_t)b_ * NS + q0 + w * 16 + g;
    #pragma unroll
    for (int nt = 0; nt < 8; nt++) {
        int cc = h_ * NDK + nt * 8 + 2 * tg;
        *(float2*)&g_cat[ mrow      * (NH * NDK) + cc] =
            make_float2(f2tff(oacc[nt][0] * inv0), f2tff(oacc[nt][1] * inv0));
        *(float2*)&g_cat[(mrow + 8) * (NH * NDK) + cc] =
            make_float2(f2tff(oacc[nt][2] * inv1), f2tff(oacc[nt][3] * inv1));
    }
}

// ---------------------------------------------------------------------------
// Kernel 3: output projection. C[8192,1024] = g_cat @ Wo + bo.
// Same pipelined 128x128 / BK=16 structure as qkv.
// ---------------------------------------------------------------------------
__global__ __launch_bounds__(256, 2) void proj_kernel(
    const float* __restrict__ bo, float* __restrict__ out)
{
    __shared__ __align__(16) float As[2 * 128 * 20];
    __shared__ __align__(16) float Bs[2 * 128 * 20];

    const int m0 = blockIdx.y * 128;
    const int n0 = blockIdx.x * 128;
    const int tid  = threadIdx.x;
    const int warp = tid >> 5, lane = tid & 31;
    const int g = lane >> 2, tg = lane & 3;
    const int wm = warp >> 1, wn = warp & 1;

    const int aoff = (lane & 15) * 20 + (lane >> 4) * 4;
    const int boff = ((lane >> 4) * 8 + (lane & 7)) * 20 + ((lane >> 3) & 1) * 4;

    const float* xb = g_cat + (size_t)m0 * ND;
    const float* wb = g_wot + (size_t)n0 * ND;
    const int sr = tid >> 2, sc = (tid & 3) * 4;

    float acc[2][8][4] = {};

    {
        cpa16(&As[sr * 20 + sc],        xb + (size_t)sr * ND + sc);
        cpa16(&As[(sr + 64) * 20 + sc], xb + (size_t)(sr + 64) * ND + sc);
        cpa16(&Bs[sr * 20 + sc],        wb + (size_t)sr * ND + sc);
        cpa16(&Bs[(sr + 64) * 20 + sc], wb + (size_t)(sr + 64) * ND + sc);
    }
    CP_COMMIT();

    for (int i = 0; i < 64; i++) {
        CP_WAIT0();
        __syncthreads();
        if (i < 63) {
            int buf = ((i + 1) & 1) * (128 * 20);
            int kk = (i + 1) * 16;
            cpa16(&As[buf + sr * 20 + sc],        xb + (size_t)sr * ND + kk + sc);
            cpa16(&As[buf + (sr + 64) * 20 + sc], xb + (size_t)(sr + 64) * ND + kk + sc);
            cpa16(&Bs[buf + sr * 20 + sc],        wb + (size_t)sr * ND + kk + sc);
            cpa16(&Bs[buf + (sr + 64) * 20 + sc], wb + (size_t)(sr + 64) * ND + kk + sc);
            CP_COMMIT();
        }
        const float* AsW = As + (i & 1) * (128 * 20) + (wm * 32) * 20;
        const float* BsW = Bs + (i & 1) * (128 * 20) + (wn * 64) * 20;
        #pragma unroll
        for (int ks = 0; ks < 2; ks++) {
            unsigned a[2][4];
            ldsm4(a[0], AsW + aoff + ks * 8);
            ldsm4(a[1], AsW + 16 * 20 + aoff + ks * 8);
            #pragma unroll
            for (int np = 0; np < 4; np++) {
                unsigned b4[4];
                ldsm4(b4, BsW + np * 16 * 20 + boff + ks * 8);
                mma8(acc[0][2 * np],     a[0], &b4[0]);
                mma8(acc[0][2 * np + 1], a[0], &b4[2]);
                mma8(acc[1][2 * np],     a[1], &b4[0]);
                mma8(acc[1][2 * np + 1], a[1], &b4[2]);
            }
        }
    }

    // Epilogue (final output fp32, no rounding)
    #pragma unroll
    for (int nt = 0; nt < 8; nt++) {
        int cc = wn * 64 + nt * 8 + 2 * tg;
        float b0 = bo[n0 + cc], b1 = bo[n0 + cc + 1];
        #pragma unroll
        for (int mt = 0; mt < 2; mt++)
            #pragma unroll
            for (int p = 0; p < 2; p++) {
                int rr = wm * 32 + mt * 16 + g + p * 8;
                float2 v;
                v.x = acc[mt][nt][2 * p + 0] + b0;
                v.y = acc[mt][nt][2 * p + 1] + b1;
                *(float2*)(out + (size_t)(m0 + rr) * ND + n0 + cc) = v;
            }
    }
}

// ---------------------------------------------------------------------------
extern "C" void kernel_launch(void* const* d_in, const int* in_sizes, int n_in,
                              void* d_out, int out_size)
{
    (void)in_sizes; (void)n_in; (void)out_size;
    const float* x  = (const float*)d_in[0];
    // d_in[1] = encoder_output (unused in the self-attention path)
    const float* Wq = (const float*)d_in[2];
    const float* bq = (const float*)d_in[3];
    const float* Wk = (const float*)d_in[4];
    const float* bk = (const float*)d_in[5];
    const float* Wv = (const float*)d_in[6];
    const float* bv = (const float*)d_in[7];
    const float* Wo = (const float*)d_in[8];
    const float* bo = (const float*)d_in[9];
    float* out = (float*)d_out;

    round_x_kernel<<<(NBS * ND) / (256 * 4), 256>>>(x);
    pack_w_kernel<<<dim3(ND / 32, NDK / 32, NH * 3), dim3(32, 8)>>>(Wq, Wk, Wv);
    pack_wo_kernel<<<dim3(ND / 32, ND / 32), dim3(32, 8)>>>(Wo);
    qkv_kernel<<<dim3(NBS / 128, (NH * 3 * NDK) / 128), 256>>>(bq, bk, bv);
    attn_kernel<<<dim3(NS / 64, NB * NH), 128>>>();
    proj_kernel<<<dim3(ND / 128, NBS / 128), 256>>>(bo, out);
}